// round 1
// baseline (speedup 1.0000x reference)
#include <cuda_runtime.h>
#include <math.h>

// Problem constants
#define B_ 32
#define T_ 2048
#define D_ 1024
#define U_ 1024

// Scratch (device globals — no allocation allowed)
__device__ float g_qproj[B_ * U_];   // query @ W2 + b2
__device__ float g_logits[B_ * T_];  // pre-softmax scores

// ---------------------------------------------------------------------------
// Kernel 1: q_proj[b,u] = sum_d query[b,d] * W2[d,u] + b2[u]
// grid (U/256, B), block 256
// ---------------------------------------------------------------------------
__global__ void qproj_kernel(const float* __restrict__ query,
                             const float* __restrict__ W2,
                             const float* __restrict__ b2)
{
    __shared__ float qs[D_];
    const int b = blockIdx.y;
    const int u = blockIdx.x * blockDim.x + threadIdx.x;
    for (int d = threadIdx.x; d < D_; d += blockDim.x)
        qs[d] = query[b * D_ + d];
    __syncthreads();

    float acc = b2[u];
#pragma unroll 8
    for (int d = 0; d < D_; ++d)
        acc = fmaf(qs[d], W2[(size_t)d * U_ + u], acc);
    g_qproj[b * U_ + u] = acc;
}

// ---------------------------------------------------------------------------
// Kernel 2 (main): fused  score[b,t] = V . tanh(values[b,t,:] @ W1 + b1 + qproj[b,:]) + bv
// Tiled fp32 GEMM: TILE_T x TILE_U output tile per u-pass, K-loop over D.
// 256 threads as 16x16; each thread owns an 8x8 micro-tile
//   rows: ty + i*16, cols: u0 + tx + j*16   (conflict-free smem reads)
// Epilogue reduces over U into per-row score partials; half-warp shuffle
// reduction across tx (16 lanes share a warp half).
// ---------------------------------------------------------------------------
#define TILE_T 128
#define TILE_U 128
#define TK 32

__global__ __launch_bounds__(256, 2) void score_kernel(
    const float* __restrict__ values,
    const float* __restrict__ W1,
    const float* __restrict__ b1,
    const float* __restrict__ V,
    const float* __restrict__ bv)
{
    __shared__ float As[TILE_T][36];   // values tile, +4 float pad (16B aligned, bank-safe)
    __shared__ float Bs[TK][TILE_U];   // W1 tile

    const int b  = blockIdx.y;
    const int t0 = blockIdx.x * TILE_T;
    const int tid = threadIdx.x;
    const int tx = tid & 15;
    const int ty = tid >> 4;

    const float* vbase = values + ((size_t)b * T_ + t0) * D_;

    float spart[8];
#pragma unroll
    for (int i = 0; i < 8; ++i) spart[i] = 0.0f;

    for (int ut = 0; ut < U_ / TILE_U; ++ut) {
        const int u0 = ut * TILE_U;

        float acc[8][8];
#pragma unroll
        for (int i = 0; i < 8; ++i)
#pragma unroll
            for (int j = 0; j < 8; ++j) acc[i][j] = 0.0f;

        for (int k0 = 0; k0 < D_; k0 += TK) {
            // Load values tile: 128 rows x 32 cols (float4, coalesced in d)
#pragma unroll
            for (int l = 0; l < 4; ++l) {
                int idx = tid + l * 256;
                int row = idx >> 3;
                int c4  = (idx & 7) * 4;
                float4 v = *(const float4*)(vbase + (size_t)row * D_ + k0 + c4);
                *(float4*)&As[row][c4] = v;
            }
            // Load W1 tile: 32 rows x 128 cols (float4, coalesced in u)
#pragma unroll
            for (int l = 0; l < 4; ++l) {
                int idx = tid + l * 256;
                int r  = idx >> 5;
                int c4 = (idx & 31) * 4;
                float4 v = *(const float4*)(W1 + (size_t)(k0 + r) * U_ + u0 + c4);
                *(float4*)&Bs[r][c4] = v;
            }
            __syncthreads();

#pragma unroll
            for (int kk = 0; kk < TK; ++kk) {
                float af[8], bf[8];
#pragma unroll
                for (int i = 0; i < 8; ++i) af[i] = As[ty + i * 16][kk];
#pragma unroll
                for (int j = 0; j < 8; ++j) bf[j] = Bs[kk][tx + j * 16];
#pragma unroll
                for (int i = 0; i < 8; ++i)
#pragma unroll
                    for (int j = 0; j < 8; ++j)
                        acc[i][j] = fmaf(af[i], bf[j], acc[i][j]);
            }
            __syncthreads();
        }

        // Epilogue for this u-tile: tanh + dot with V, fold into row partials
        float cu[8], vv[8];
#pragma unroll
        for (int j = 0; j < 8; ++j) {
            int u = u0 + tx + j * 16;
            cu[j] = b1[u] + g_qproj[b * U_ + u];
            vv[j] = V[u];
        }
#pragma unroll
        for (int i = 0; i < 8; ++i) {
#pragma unroll
            for (int j = 0; j < 8; ++j)
                spart[i] = fmaf(tanhf(acc[i][j] + cu[j]), vv[j], spart[i]);
        }
    }

    // Reduce partials across the 16 tx lanes (contiguous half-warp)
    const float bvv = bv[0];
#pragma unroll
    for (int i = 0; i < 8; ++i) {
        float p = spart[i];
#pragma unroll
        for (int off = 8; off > 0; off >>= 1)
            p += __shfl_down_sync(0xffffffffu, p, off, 16);
        if (tx == 0)
            g_logits[b * T_ + t0 + ty + i * 16] = p + bvv;
    }
}

// ---------------------------------------------------------------------------
// Kernel 3: softmax over T per batch; writes attention_weights
// grid B, block 256
// ---------------------------------------------------------------------------
__global__ void softmax_kernel(float* __restrict__ weights)
{
    __shared__ float red[256];
    const int b = blockIdx.x;
    const int tid = threadIdx.x;

    float m = -INFINITY;
    for (int t = tid; t < T_; t += 256)
        m = fmaxf(m, g_logits[b * T_ + t]);
    red[tid] = m;
    __syncthreads();
    for (int s = 128; s > 0; s >>= 1) {
        if (tid < s) red[tid] = fmaxf(red[tid], red[tid + s]);
        __syncthreads();
    }
    m = red[0];
    __syncthreads();

    float sum = 0.0f;
    for (int t = tid; t < T_; t += 256)
        sum += expf(g_logits[b * T_ + t] - m);
    red[tid] = sum;
    __syncthreads();
    for (int s = 128; s > 0; s >>= 1) {
        if (tid < s) red[tid] += red[tid + s];
        __syncthreads();
    }
    const float inv = 1.0f / red[0];

    for (int t = tid; t < T_; t += 256)
        weights[b * T_ + t] = expf(g_logits[b * T_ + t] - m) * inv;
}

// ---------------------------------------------------------------------------
// Kernel 4: context[b,d] = sum_t weights[b,t] * values[b,t,d]
// grid (D/128, B), block 128. weights row cached in smem.
// ---------------------------------------------------------------------------
__global__ void context_kernel(const float* __restrict__ values,
                               const float* __restrict__ weights,
                               float* __restrict__ context)
{
    __shared__ float w[T_];
    const int b = blockIdx.y;
    const int d = blockIdx.x * blockDim.x + threadIdx.x;

    for (int t = threadIdx.x; t < T_; t += blockDim.x)
        w[t] = weights[b * T_ + t];
    __syncthreads();

    const float* vp = values + (size_t)b * T_ * D_ + d;
    float acc0 = 0.0f, acc1 = 0.0f, acc2 = 0.0f, acc3 = 0.0f;
#pragma unroll 2
    for (int t = 0; t < T_; t += 4) {
        acc0 = fmaf(w[t + 0], vp[(size_t)(t + 0) * D_], acc0);
        acc1 = fmaf(w[t + 1], vp[(size_t)(t + 1) * D_], acc1);
        acc2 = fmaf(w[t + 2], vp[(size_t)(t + 2) * D_], acc2);
        acc3 = fmaf(w[t + 3], vp[(size_t)(t + 3) * D_], acc3);
    }
    context[b * D_ + d] = (acc0 + acc1) + (acc2 + acc3);
}

// ---------------------------------------------------------------------------
// Launch
// ---------------------------------------------------------------------------
extern "C" void kernel_launch(void* const* d_in, const int* in_sizes, int n_in,
                              void* d_out, int out_size)
{
    const float* query  = (const float*)d_in[0];
    const float* values = (const float*)d_in[1];
    const float* W1     = (const float*)d_in[2];
    const float* b1     = (const float*)d_in[3];
    const float* W2     = (const float*)d_in[4];
    const float* b2     = (const float*)d_in[5];
    const float* V      = (const float*)d_in[6];
    const float* bv     = (const float*)d_in[7];

    float* out     = (float*)d_out;
    float* context = out;             // [B, D]   = 32768 floats
    float* weights = out + B_ * D_;   // [B, T, 1] = 65536 floats

    qproj_kernel<<<dim3(U_ / 256, B_), 256>>>(query, W2, b2);
    score_kernel<<<dim3(T_ / TILE_T, B_), 256>>>(values, W1, b1, V, bv);
    softmax_kernel<<<B_, 256>>>(weights);
    context_kernel<<<dim3(D_ / 128, B_), 128>>>(values, weights, context);
}

// round 4
// speedup vs baseline: 3.0532x; 3.0532x over previous
#include <cuda_runtime.h>
#include <cuda_bf16.h>
#include <math.h>
#include <stdint.h>

#define B_ 32
#define T_ 2048
#define D_ 1024
#define U_ 1024

// ---------------- device scratch (no allocation allowed) ----------------
__device__ float          g_qproj[B_ * U_];        // query @ W2 + b2
__device__ float          g_logits[B_ * T_];       // pre-softmax scores
__device__ __nv_bfloat16  g_w1t[U_ * D_];          // W1^T in bf16  [U, D]
__device__ float          g_cpart[8 * B_ * D_];    // context partials

// ---------------- helpers ----------------
__device__ __forceinline__ uint32_t smem_u32(const void* p) {
    uint32_t a;
    asm("{ .reg .u64 t; cvta.to.shared.u64 t, %1; cvt.u32.u64 %0, t; }" : "=r"(a) : "l"(p));
    return a;
}
// pack two fp32 -> bf16x2 (lo in low half, hi in high half)
__device__ __forceinline__ uint32_t pack_bf16x2(float lo, float hi) {
    uint32_t r;
    asm("cvt.rn.bf16x2.f32 %0, %1, %2;" : "=r"(r) : "f"(hi), "f"(lo));
    return r;
}
__device__ __forceinline__ void ldsm_x4(uint32_t& r0, uint32_t& r1, uint32_t& r2, uint32_t& r3,
                                        uint32_t addr) {
    asm volatile("ldmatrix.sync.aligned.m8n8.x4.shared.b16 {%0,%1,%2,%3}, [%4];"
                 : "=r"(r0), "=r"(r1), "=r"(r2), "=r"(r3) : "r"(addr));
}
__device__ __forceinline__ void mma16816(float* c, const uint32_t* a, uint32_t b0, uint32_t b1) {
    asm volatile(
        "mma.sync.aligned.m16n8k16.row.col.f32.bf16.bf16.f32 "
        "{%0,%1,%2,%3},{%4,%5,%6,%7},{%8,%9},{%0,%1,%2,%3};"
        : "+f"(c[0]), "+f"(c[1]), "+f"(c[2]), "+f"(c[3])
        : "r"(a[0]), "r"(a[1]), "r"(a[2]), "r"(a[3]), "r"(b0), "r"(b1));
}

// ---------------------------------------------------------------------------
// W1 [D,U] fp32 -> g_w1t [U,D] bf16 (transpose + convert)
// ---------------------------------------------------------------------------
__global__ void w1t_kernel(const float* __restrict__ W1)
{
    __shared__ float tile[32][33];
    const int u0 = blockIdx.x * 32, d0 = blockIdx.y * 32;
    const int tx = threadIdx.x, ty = threadIdx.y;
#pragma unroll
    for (int i = 0; i < 32; i += 8)
        tile[ty + i][tx] = W1[(size_t)(d0 + ty + i) * U_ + u0 + tx];
    __syncthreads();
#pragma unroll
    for (int i = 0; i < 32; i += 8)
        g_w1t[(size_t)(u0 + ty + i) * D_ + d0 + tx] = __float2bfloat16(tile[tx][ty + i]);
}

// ---------------------------------------------------------------------------
// q_proj
// ---------------------------------------------------------------------------
__global__ void qproj_kernel(const float* __restrict__ query,
                             const float* __restrict__ W2,
                             const float* __restrict__ b2)
{
    __shared__ float qs[D_];
    const int b = blockIdx.y;
    const int u = blockIdx.x * blockDim.x + threadIdx.x;
    for (int d = threadIdx.x; d < D_; d += blockDim.x)
        qs[d] = query[b * D_ + d];
    __syncthreads();
    float acc = b2[u];
#pragma unroll 8
    for (int d = 0; d < D_; ++d)
        acc = fmaf(qs[d], W2[(size_t)d * U_ + u], acc);
    g_qproj[b * U_ + u] = acc;
}

// ---------------------------------------------------------------------------
// Fused score GEMM (mma.sync bf16):
//   logits[b,t] = V . tanh(values[b,t,:] @ W1 + b1 + qproj[b,:]) + bv
// CTA: 64 t-rows, A (64x1024 bf16) resident in smem; 8 passes over U (128 u
// each); B (W1^T bf16, K-contig) streamed in 16 double-buffered 16KB chunks.
// 8 warps: warp_m in {0,1} x 32 rows, warp_n in {0..3} x 32 cols.
// Epilogue folds tanh(acc+cu)*V into per-row partials from mma fragments.
// ---------------------------------------------------------------------------
#define SMA    0                       // 64 x 2048B = 131072
#define SMB0   131072                  // 128 x 128B = 16384
#define SMB1   (SMB0 + 16384)
#define SMCU   (SMB1 + 16384)          // 1024 f32
#define SMV    (SMCU + 4096)           // 1024 f32
#define SMRED  (SMV + 4096)            // 64 x 4 f32
#define SMTOT  (SMRED + 1024)

__global__ void __launch_bounds__(256, 1)
score_kernel(const float* __restrict__ values,
             const float* __restrict__ b1,
             const float* __restrict__ V,
             const float* __restrict__ bv)
{
    extern __shared__ char smem[];
    const uint32_t sb = smem_u32(smem);
    const int tid  = threadIdx.x;
    const int lane = tid & 31;
    const int warp = tid >> 5;
    const int warp_m = warp & 1;
    const int warp_n = warp >> 1;
    const int g  = lane >> 2;
    const int t4 = lane & 3;

    const int b  = blockIdx.x >> 5;          // 32 t-tiles per batch
    const int t0 = (blockIdx.x & 31) * 64;

    float* cu_s = (float*)(smem + SMCU);
    float* V_s  = (float*)(smem + SMV);
    float* sred = (float*)(smem + SMRED);

    // per-batch column constants
    for (int u = tid; u < U_; u += 256) {
        cu_s[u] = b1[u] + g_qproj[b * U_ + u];
        V_s[u]  = V[u];
    }

    // ---- A resident: 64 rows x 1024 k, fp32 -> bf16, xor-swizzled ----
    const float* vbase = values + ((size_t)b * T_ + t0) * D_;
#pragma unroll 4
    for (int it = 0; it < 32; ++it) {
        int idx = tid + it * 256;             // 8192 slots of 8 bf16
        int row = idx >> 7;
        int c   = idx & 127;
        const float* src = vbase + (size_t)row * D_ + c * 8;
        float4 f0 = *(const float4*)(src);
        float4 f1 = *(const float4*)(src + 4);
        uint4 o;
        o.x = pack_bf16x2(f0.x, f0.y);
        o.y = pack_bf16x2(f0.z, f0.w);
        o.z = pack_bf16x2(f1.x, f1.y);
        o.w = pack_bf16x2(f1.z, f1.w);
        *(uint4*)(smem + SMA + row * 2048 + ((c ^ (row & 7)) << 4)) = o;
    }
    __syncthreads();

    char* const bbuf[2] = {smem + SMB0, smem + SMB1};
    float spart[4] = {0.f, 0.f, 0.f, 0.f};

    for (int pass = 0; pass < 8; ++pass) {
        const int u0 = pass * 128;
        const __nv_bfloat16* wbase = g_w1t + (size_t)u0 * D_;

        float acc[2][4][4];
#pragma unroll
        for (int mt = 0; mt < 2; ++mt)
#pragma unroll
            for (int j = 0; j < 4; ++j)
#pragma unroll
                for (int r = 0; r < 4; ++r) acc[mt][j][r] = 0.f;

        // prime chunk 0
        {
            char* dst = bbuf[0];
#pragma unroll
            for (int j2 = 0; j2 < 4; ++j2) {
                int idx = tid + j2 * 256;          // 1024 slots
                int row = idx >> 3, c = idx & 7;
                uint4 v = *(const uint4*)(wbase + (size_t)row * D_ + c * 8);
                *(uint4*)(dst + row * 128 + ((c ^ (row & 7)) << 4)) = v;
            }
        }
        __syncthreads();

        for (int kc = 0; kc < 16; ++kc) {
            if (kc < 15) {
                char* dst = bbuf[(kc + 1) & 1];
                const __nv_bfloat16* src = wbase + (kc + 1) * 64;
#pragma unroll
                for (int j2 = 0; j2 < 4; ++j2) {
                    int idx = tid + j2 * 256;
                    int row = idx >> 3, c = idx & 7;
                    uint4 v = *(const uint4*)(src + (size_t)row * D_ + c * 8);
                    *(uint4*)(dst + row * 128 + ((c ^ (row & 7)) << 4)) = v;
                }
            }
            const uint32_t bbase = sb + (uint32_t)(bbuf[kc & 1] - smem);

#pragma unroll
            for (int ks = 0; ks < 4; ++ks) {
                const int kkA = kc * 4 + ks;
                uint32_t a[2][4];
#pragma unroll
                for (int mt = 0; mt < 2; ++mt) {
                    int row = warp_m * 32 + mt * 16 + (lane & 15);
                    int c   = kkA * 2 + (lane >> 4);
                    uint32_t addr = sb + SMA + row * 2048 + ((c ^ (row & 7)) << 4);
                    ldsm_x4(a[mt][0], a[mt][1], a[mt][2], a[mt][3], addr);
                }
#pragma unroll
                for (int nt = 0; nt < 2; ++nt) {
                    int row = warp_n * 32 + nt * 16 + (lane & 15);
                    int c   = ks * 2 + (lane >> 4);
                    uint32_t addr = bbase + row * 128 + ((c ^ (row & 7)) << 4);
                    uint32_t r0, r1, r2, r3;
                    ldsm_x4(r0, r1, r2, r3, addr);
#pragma unroll
                    for (int mt = 0; mt < 2; ++mt) {
                        mma16816(acc[mt][nt * 2 + 0], a[mt], r0, r2);  // cols n0-7
                        mma16816(acc[mt][nt * 2 + 1], a[mt], r1, r3);  // cols n8-15
                    }
                }
            }
            __syncthreads();
        }

        // ---- epilogue: tanh + dot V folded into per-row partials ----
#pragma unroll
        for (int mt = 0; mt < 2; ++mt)
#pragma unroll
            for (int j = 0; j < 4; ++j)
#pragma unroll
                for (int r = 0; r < 4; ++r) {
                    int u = u0 + warp_n * 32 + j * 8 + t4 * 2 + (r & 1);
                    float x = acc[mt][j][r] + cu_s[u];
                    spart[mt * 2 + (r >> 1)] = fmaf(tanhf(x), V_s[u], spart[mt * 2 + (r >> 1)]);
                }
    }

    // reduce across quad lanes (cols), stash per-warp_n partials
#pragma unroll
    for (int s = 0; s < 4; ++s) {
        float v = spart[s];
        v += __shfl_xor_sync(0xffffffffu, v, 1);
        v += __shfl_xor_sync(0xffffffffu, v, 2);
        if (t4 == 0) {
            int row = warp_m * 32 + (s >> 1) * 16 + (s & 1) * 8 + g;
            sred[row * 4 + warp_n] = v;
        }
    }
    __syncthreads();
    if (tid < 64) {
        const float* rp = &sred[tid * 4];
        g_logits[b * T_ + t0 + tid] = (rp[0] + rp[1]) + (rp[2] + rp[3]) + bv[0];
    }
}

// ---------------------------------------------------------------------------
// softmax over T per batch
// ---------------------------------------------------------------------------
__global__ void softmax_kernel(float* __restrict__ weights)
{
    __shared__ float red[256];
    const int b = blockIdx.x;
    const int tid = threadIdx.x;

    float m = -INFINITY;
    for (int t = tid; t < T_; t += 256)
        m = fmaxf(m, g_logits[b * T_ + t]);
    red[tid] = m;
    __syncthreads();
    for (int s = 128; s > 0; s >>= 1) {
        if (tid < s) red[tid] = fmaxf(red[tid], red[tid + s]);
        __syncthreads();
    }
    m = red[0];
    __syncthreads();

    float sum = 0.0f;
    for (int t = tid; t < T_; t += 256)
        sum += expf(g_logits[b * T_ + t] - m);
    red[tid] = sum;
    __syncthreads();
    for (int s = 128; s > 0; s >>= 1) {
        if (tid < s) red[tid] += red[tid + s];
        __syncthreads();
    }
    const float inv = 1.0f / red[0];

    for (int t = tid; t < T_; t += 256)
        weights[b * T_ + t] = expf(g_logits[b * T_ + t] - m) * inv;
}

// ---------------------------------------------------------------------------
// context: two-stage deterministic reduction over T
// ---------------------------------------------------------------------------
__global__ void context_part_kernel(const float* __restrict__ values,
                                    const float* __restrict__ weights)
{
    __shared__ float w[256];
    const int b = blockIdx.y;
    const int chunk = blockIdx.z;
    const int d = blockIdx.x * 128 + threadIdx.x;
    const int tbase = chunk * 256;

    for (int t = threadIdx.x; t < 256; t += 128)
        w[t] = weights[b * T_ + tbase + t];
    __syncthreads();

    const float* vp = values + ((size_t)b * T_ + tbase) * D_ + d;
    float a0 = 0.f, a1 = 0.f, a2 = 0.f, a3 = 0.f;
#pragma unroll 4
    for (int t = 0; t < 256; t += 4) {
        a0 = fmaf(w[t + 0], vp[(size_t)(t + 0) * D_], a0);
        a1 = fmaf(w[t + 1], vp[(size_t)(t + 1) * D_], a1);
        a2 = fmaf(w[t + 2], vp[(size_t)(t + 2) * D_], a2);
        a3 = fmaf(w[t + 3], vp[(size_t)(t + 3) * D_], a3);
    }
    g_cpart[(chunk * B_ + b) * D_ + d] = (a0 + a1) + (a2 + a3);
}

__global__ void context_reduce_kernel(float* __restrict__ context)
{
    const int i = blockIdx.x * 256 + threadIdx.x;   // over B*D
    float s = 0.0f;
#pragma unroll
    for (int c = 0; c < 8; ++c)
        s += g_cpart[c * (B_ * D_) + i];
    context[i] = s;
}

// ---------------------------------------------------------------------------
extern "C" void kernel_launch(void* const* d_in, const int* in_sizes, int n_in,
                              void* d_out, int out_size)
{
    const float* query  = (const float*)d_in[0];
    const float* values = (const float*)d_in[1];
    const float* W1     = (const float*)d_in[2];
    const float* b1     = (const float*)d_in[3];
    const float* W2     = (const float*)d_in[4];
    const float* b2     = (const float*)d_in[5];
    const float* V      = (const float*)d_in[6];
    const float* bv     = (const float*)d_in[7];

    float* out     = (float*)d_out;
    float* context = out;             // [B, D]
    float* weights = out + B_ * D_;   // [B, T, 1]

    cudaFuncSetAttribute(score_kernel,
                         cudaFuncAttributeMaxDynamicSharedMemorySize, SMTOT);

    w1t_kernel<<<dim3(U_ / 32, D_ / 32), dim3(32, 8)>>>(W1);
    qproj_kernel<<<dim3(U_ / 256, B_), 256>>>(query, W2, b2);
    score_kernel<<<(B_ * T_) / 64, 256, SMTOT>>>(values, b1, V, bv);
    softmax_kernel<<<B_, 256>>>(weights);
    context_part_kernel<<<dim3(D_ / 128, B_, 8), 128>>>(values, weights);
    context_reduce_kernel<<<(B_ * D_) / 256, 256>>>(context);
}

// round 5
// speedup vs baseline: 6.5471x; 2.1443x over previous
#include <cuda_runtime.h>
#include <cuda_fp16.h>
#include <math.h>
#include <stdint.h>

#define B_ 32
#define T_ 2048
#define D_ 1024
#define U_ 1024

// ---------------- device scratch (no allocation allowed) ----------------
__device__ float   g_qproj[B_ * U_];     // query @ W2 + b2
__device__ float   g_logits[B_ * T_];    // pre-softmax scores
__device__ __half  g_w1t[U_ * D_];       // W1^T in fp16  [U, D]
__device__ float   g_cpart[8 * B_ * D_]; // context partials

// ---------------- helpers ----------------
__device__ __forceinline__ uint32_t smem_u32(const void* p) {
    uint32_t a;
    asm("{ .reg .u64 t; cvta.to.shared.u64 t, %1; cvt.u32.u64 %0, t; }" : "=r"(a) : "l"(p));
    return a;
}
// pack two fp32 -> f16x2 (lo in low half, hi in high half)
__device__ __forceinline__ uint32_t pack_f16x2(float lo, float hi) {
    uint32_t r;
    asm("cvt.rn.f16x2.f32 %0, %1, %2;" : "=r"(r) : "f"(hi), "f"(lo));
    return r;
}
__device__ __forceinline__ void ldsm_x4(uint32_t& r0, uint32_t& r1, uint32_t& r2, uint32_t& r3,
                                        uint32_t addr) {
    asm volatile("ldmatrix.sync.aligned.m8n8.x4.shared.b16 {%0,%1,%2,%3}, [%4];"
                 : "=r"(r0), "=r"(r1), "=r"(r2), "=r"(r3) : "r"(addr));
}
__device__ __forceinline__ void mma16816(float* c, const uint32_t* a, uint32_t b0, uint32_t b1) {
    asm volatile(
        "mma.sync.aligned.m16n8k16.row.col.f32.f16.f16.f32 "
        "{%0,%1,%2,%3},{%4,%5,%6,%7},{%8,%9},{%0,%1,%2,%3};"
        : "+f"(c[0]), "+f"(c[1]), "+f"(c[2]), "+f"(c[3])
        : "r"(a[0]), "r"(a[1]), "r"(a[2]), "r"(a[3]), "r"(b0), "r"(b1));
}
__device__ __forceinline__ void cp_async16(uint32_t sdst, const void* gsrc) {
    asm volatile("cp.async.cg.shared.global [%0], [%1], 16;" :: "r"(sdst), "l"(gsrc));
}
__device__ __forceinline__ void cp_commit() {
    asm volatile("cp.async.commit_group;" ::: "memory");
}
__device__ __forceinline__ void cp_wait1() {
    asm volatile("cp.async.wait_group 1;" ::: "memory");
}

// ---------------------------------------------------------------------------
// W1 [D,U] fp32 -> g_w1t [U,D] fp16 (transpose + convert)
// ---------------------------------------------------------------------------
__global__ void w1t_kernel(const float* __restrict__ W1)
{
    __shared__ float tile[32][33];
    const int u0 = blockIdx.x * 32, d0 = blockIdx.y * 32;
    const int tx = threadIdx.x, ty = threadIdx.y;
#pragma unroll
    for (int i = 0; i < 32; i += 8)
        tile[ty + i][tx] = W1[(size_t)(d0 + ty + i) * U_ + u0 + tx];
    __syncthreads();
#pragma unroll
    for (int i = 0; i < 32; i += 8)
        g_w1t[(size_t)(u0 + ty + i) * D_ + d0 + tx] = __float2half_rn(tile[tx][ty + i]);
}

// ---------------------------------------------------------------------------
// q_proj
// ---------------------------------------------------------------------------
__global__ void qproj_kernel(const float* __restrict__ query,
                             const float* __restrict__ W2,
                             const float* __restrict__ b2)
{
    __shared__ float qs[D_];
    const int b = blockIdx.y;
    const int u = blockIdx.x * blockDim.x + threadIdx.x;
    for (int d = threadIdx.x; d < D_; d += blockDim.x)
        qs[d] = query[b * D_ + d];
    __syncthreads();
    float acc = b2[u];
#pragma unroll 8
    for (int d = 0; d < D_; ++d)
        acc = fmaf(qs[d], W2[(size_t)d * U_ + u], acc);
    g_qproj[b * U_ + u] = acc;
}

// ---------------------------------------------------------------------------
// Fused score GEMM (mma.sync fp16), cp.async-pipelined:
//   logits[b,t] = V . tanh(values[b,t,:] @ W1 + b1 + qproj[b,:]) + bv
// CTA: 64 t-rows; A (64x1024 fp16) resident in smem. 4 passes over U
// (256 u each); B (W1^T fp16, K-contig) streamed in 16 chunks of 256x64
// per pass via 2-stage cp.async double buffer. Next pass's prologue is
// issued inside the kc loop so the tanh epilogue overlaps the loads.
// 8 warps: warp_m in {0,1} x 32 rows, warp_n in {0..3} x 64 cols.
// ---------------------------------------------------------------------------
#define SMA    0                       // 64 x 2048B = 131072
#define SMB0   131072                  // 256 x 128B = 32768
#define SMB1   (SMB0 + 32768)
#define SMCU   (SMB1 + 32768)          // 1024 f32
#define SMV    (SMCU + 4096)           // 1024 f32
#define SMRED  (SMV + 4096)            // 64 x 4 f32
#define SMTOT  (SMRED + 1024)

__global__ void __launch_bounds__(256, 1)
score_kernel(const float* __restrict__ values,
             const float* __restrict__ b1,
             const float* __restrict__ V,
             const float* __restrict__ bv)
{
    extern __shared__ char smem[];
    const uint32_t sb = smem_u32(smem);
    const int tid  = threadIdx.x;
    const int lane = tid & 31;
    const int warp = tid >> 5;
    const int warp_m = warp & 1;
    const int warp_n = warp >> 1;
    const int g  = lane >> 2;
    const int t4 = lane & 3;

    const int b  = blockIdx.x >> 5;          // 32 t-tiles per batch
    const int t0 = (blockIdx.x & 31) * 64;

    float* cu_s = (float*)(smem + SMCU);
    float* V_s  = (float*)(smem + SMV);
    float* sred = (float*)(smem + SMRED);

    // per-batch column constants
    for (int u = tid; u < U_; u += 256) {
        cu_s[u] = b1[u] + g_qproj[b * U_ + u];
        V_s[u]  = V[u];
    }

    // ---- A resident: 64 rows x 1024 k, fp32 -> fp16, xor-swizzled ----
    const float* vbase = values + ((size_t)b * T_ + t0) * D_;
#pragma unroll 4
    for (int it = 0; it < 32; ++it) {
        int idx = tid + it * 256;             // 8192 slots of 8 fp16
        int row = idx >> 7;
        int c   = idx & 127;
        const float* src = vbase + (size_t)row * D_ + c * 8;
        float4 f0 = *(const float4*)(src);
        float4 f1 = *(const float4*)(src + 4);
        uint4 o;
        o.x = pack_f16x2(f0.x, f0.y);
        o.y = pack_f16x2(f0.z, f0.w);
        o.z = pack_f16x2(f1.x, f1.y);
        o.w = pack_f16x2(f1.z, f1.w);
        *(uint4*)(smem + SMA + row * 2048 + ((c ^ (row & 7)) << 4)) = o;
    }

    // issue pass-0 prologue (chunks 0,1) while A store completes
    const uint32_t boff[2] = {SMB0, SMB1};
    auto issue_chunk = [&](int pass, int kc) {
        const __half* src0 = g_w1t + (size_t)(pass * 256) * D_ + kc * 64;
        uint32_t dbase = sb + boff[kc & 1];
#pragma unroll
        for (int j = 0; j < 8; ++j) {
            int idx = tid + j * 256;          // 2048 slots of 16B
            int row = idx >> 3, c = idx & 7;
            cp_async16(dbase + row * 128 + ((c ^ (row & 7)) << 4),
                       src0 + (size_t)row * D_ + c * 8);
        }
    };
    issue_chunk(0, 0); cp_commit();
    issue_chunk(0, 1); cp_commit();
    __syncthreads();

    float spart[4] = {0.f, 0.f, 0.f, 0.f};

    for (int pass = 0; pass < 4; ++pass) {
        const int u0 = pass * 256;

        float acc[2][8][4];
#pragma unroll
        for (int mt = 0; mt < 2; ++mt)
#pragma unroll
            for (int j = 0; j < 8; ++j)
#pragma unroll
                for (int r = 0; r < 4; ++r) acc[mt][j][r] = 0.f;

        for (int kc = 0; kc < 16; ++kc) {
            cp_wait1();
            __syncthreads();
            const uint32_t bbase = sb + boff[kc & 1];

#pragma unroll
            for (int ks = 0; ks < 4; ++ks) {
                const int kk = kc * 4 + ks;
                uint32_t a[2][4];
#pragma unroll
                for (int mt = 0; mt < 2; ++mt) {
                    int row = warp_m * 32 + mt * 16 + (lane & 15);
                    int c   = kk * 2 + (lane >> 4);
                    uint32_t addr = sb + SMA + row * 2048 + ((c ^ (row & 7)) << 4);
                    ldsm_x4(a[mt][0], a[mt][1], a[mt][2], a[mt][3], addr);
                }
#pragma unroll
                for (int nt = 0; nt < 4; ++nt) {
                    int row = warp_n * 64 + nt * 16 + (lane & 15);
                    int c   = ks * 2 + (lane >> 4);
                    uint32_t addr = bbase + row * 128 + ((c ^ (row & 7)) << 4);
                    uint32_t r0, r1, r2, r3;
                    ldsm_x4(r0, r1, r2, r3, addr);
#pragma unroll
                    for (int mt = 0; mt < 2; ++mt) {
                        mma16816(acc[mt][nt * 2 + 0], a[mt], r0, r2);  // cols +0..7
                        mma16816(acc[mt][nt * 2 + 1], a[mt], r1, r3);  // cols +8..15
                    }
                }
            }
            __syncthreads();
            // refill the buffer just consumed: chunk kc+2 of this pass, or
            // the next pass's prologue (kc=14 -> c0, kc=15 -> c1)
            if (kc + 2 < 16)       issue_chunk(pass, kc + 2);
            else if (pass + 1 < 4) issue_chunk(pass + 1, kc + 2 - 16);
            cp_commit();
        }

        // ---- epilogue: tanh + dot V folded into per-row partials ----
#pragma unroll
        for (int mt = 0; mt < 2; ++mt)
#pragma unroll
            for (int j = 0; j < 8; ++j)
#pragma unroll
                for (int r = 0; r < 4; ++r) {
                    int u = u0 + warp_n * 64 + j * 8 + t4 * 2 + (r & 1);
                    float x = acc[mt][j][r] + cu_s[u];
                    spart[mt * 2 + (r >> 1)] = fmaf(tanhf(x), V_s[u], spart[mt * 2 + (r >> 1)]);
                }
    }

    // reduce across quad lanes (cols), stash per-warp_n partials
#pragma unroll
    for (int s = 0; s < 4; ++s) {
        float v = spart[s];
        v += __shfl_xor_sync(0xffffffffu, v, 1);
        v += __shfl_xor_sync(0xffffffffu, v, 2);
        if (t4 == 0) {
            int row = warp_m * 32 + (s >> 1) * 16 + (s & 1) * 8 + g;
            sred[row * 4 + warp_n] = v;
        }
    }
    __syncthreads();
    if (tid < 64) {
        const float* rp = &sred[tid * 4];
        g_logits[b * T_ + t0 + tid] = (rp[0] + rp[1]) + (rp[2] + rp[3]) + bv[0];
    }
}

// ---------------------------------------------------------------------------
// softmax over T per batch
// ---------------------------------------------------------------------------
__global__ void softmax_kernel(float* __restrict__ weights)
{
    __shared__ float red[256];
    const int b = blockIdx.x;
    const int tid = threadIdx.x;

    float m = -INFINITY;
    for (int t = tid; t < T_; t += 256)
        m = fmaxf(m, g_logits[b * T_ + t]);
    red[tid] = m;
    __syncthreads();
    for (int s = 128; s > 0; s >>= 1) {
        if (tid < s) red[tid] = fmaxf(red[tid], red[tid + s]);
        __syncthreads();
    }
    m = red[0];
    __syncthreads();

    float sum = 0.0f;
    for (int t = tid; t < T_; t += 256)
        sum += expf(g_logits[b * T_ + t] - m);
    red[tid] = sum;
    __syncthreads();
    for (int s = 128; s > 0; s >>= 1) {
        if (tid < s) red[tid] += red[tid + s];
        __syncthreads();
    }
    const float inv = 1.0f / red[0];

    for (int t = tid; t < T_; t += 256)
        weights[b * T_ + t] = expf(g_logits[b * T_ + t] - m) * inv;
}

// ---------------------------------------------------------------------------
// context: two-stage deterministic reduction over T
// ---------------------------------------------------------------------------
__global__ void context_part_kernel(const float* __restrict__ values,
                                    const float* __restrict__ weights)
{
    __shared__ float w[256];
    const int b = blockIdx.y;
    const int chunk = blockIdx.z;
    const int d = blockIdx.x * 128 + threadIdx.x;
    const int tbase = chunk * 256;

    for (int t = threadIdx.x; t < 256; t += 128)
        w[t] = weights[b * T_ + tbase + t];
    __syncthreads();

    const float* vp = values + ((size_t)b * T_ + tbase) * D_ + d;
    float a0 = 0.f, a1 = 0.f, a2 = 0.f, a3 = 0.f;
#pragma unroll 4
    for (int t = 0; t < 256; t += 4) {
        a0 = fmaf(w[t + 0], vp[(size_t)(t + 0) * D_], a0);
        a1 = fmaf(w[t + 1], vp[(size_t)(t + 1) * D_], a1);
        a2 = fmaf(w[t + 2], vp[(size_t)(t + 2) * D_], a2);
        a3 = fmaf(w[t + 3], vp[(size_t)(t + 3) * D_], a3);
    }
    g_cpart[(chunk * B_ + b) * D_ + d] = (a0 + a1) + (a2 + a3);
}

__global__ void context_reduce_kernel(float* __restrict__ context)
{
    const int i = blockIdx.x * 256 + threadIdx.x;   // over B*D
    float s = 0.0f;
#pragma unroll
    for (int c = 0; c < 8; ++c)
        s += g_cpart[c * (B_ * D_) + i];
    context[i] = s;
}

// ---------------------------------------------------------------------------
extern "C" void kernel_launch(void* const* d_in, const int* in_sizes, int n_in,
                              void* d_out, int out_size)
{
    const float* query  = (const float*)d_in[0];
    const float* values = (const float*)d_in[1];
    const float* W1     = (const float*)d_in[2];
    const float* b1     = (const float*)d_in[3];
    const float* W2     = (const float*)d_in[4];
    const float* b2     = (const float*)d_in[5];
    const float* V      = (const float*)d_in[6];
    const float* bv     = (const float*)d_in[7];

    float* out     = (float*)d_out;
    float* context = out;             // [B, D]
    float* weights = out + B_ * D_;   // [B, T, 1]

    cudaFuncSetAttribute(score_kernel,
                         cudaFuncAttributeMaxDynamicSharedMemorySize, SMTOT);

    w1t_kernel<<<dim3(U_ / 32, D_ / 32), dim3(32, 8)>>>(W1);
    qproj_kernel<<<dim3(U_ / 256, B_), 256>>>(query, W2, b2);
    score_kernel<<<(B_ * T_) / 64, 256, SMTOT>>>(values, b1, V, bv);
    softmax_kernel<<<B_, 256>>>(weights);
    context_part_kernel<<<dim3(D_ / 128, B_, 8), 128>>>(values, weights);
    context_reduce_kernel<<<(B_ * D_) / 256, 256>>>(context);
}